// round 16
// baseline (speedup 1.0000x reference)
#include <cuda_runtime.h>
#include <cuda_bf16.h>
#include <math.h>

#define NN 512
#define DD 384
#define EE 128
#define HH 8
#define CATD 1280
#define HID 768
#define PSTR 704

static __device__ __constant__ float SCAL_SCALE = 0.14433756729740643f; // (3*16)^-0.5
static __device__ __constant__ float POINT_SCALE = 0.13608276348795434f; // (3*4*4.5)^-0.5
static __device__ __constant__ float PAIR_SCALE = 0.5773502691896258f;  // 3^-0.5

// scratch
__device__ float g_zero[PSTR];               // static zero (never written)
__device__ float g_proj[NN*PSTR];
__device__ float g_qs[NN*128];
__device__ float g_kkT[128*NN];   // [h*16+k][j]
__device__ float g_vs[NN*128];
__device__ float g_qp[NN*96];
__device__ float g_kpT[96*NN];    // [h*12+q][j]
__device__ float g_vp[NN*96];
__device__ float g_q2[HH*NN];
__device__ float g_k2[HH*NN];
__device__ float g_attn[(size_t)HH*NN*NN];   // exp(raw - m_chunk)
__device__ float g_mc[HH*NN*8];
__device__ float g_sc[HH*NN*8];
__device__ float g_pts[NN*96];
__device__ float g_rpp[(size_t)8*NN*1024];
__device__ float g_cat[(size_t)NN*CATD];
__device__ float g_t0[NN*DD];
__device__ float g_t1[NN*DD];
__device__ float g_t2[NN*DD];
__device__ float g_t3[NN*DD];
__device__ float g_u0[NN*HID];
__device__ float g_u1[NN*HID];
__device__ float g_u2[NN*HID];
__device__ float g_u3[NN*HID];
__device__ float g_v0[NN*HID];
__device__ float g_v1[NN*HID];
__device__ float g_v2[NN*HID];
__device__ float g_v3[NN*HID];
__device__ float g_x1[NN*DD];

// ---------------------------------------------------------------------------
// K_post: scatter proj results, rigid transforms, q2/k2. One block per i.
// ---------------------------------------------------------------------------
__global__ void k_post(const float* __restrict__ rot,
                       const float* __restrict__ trans) {
    int i = blockIdx.x, t = threadIdx.x; // 128
    __shared__ float pg[192];
    const float* pr = &g_proj[i*PSTR];

    float a = pr[t];
    g_qs[i*128 + t] = a;
    g_kkT[t*NN + i] = pr[128 + t];
    g_vs[i*128 + t] = pr[256 + t];

    const float* R = &rot[i*9];
    float T[3] = {trans[i*3], trans[i*3+1], trans[i*3+2]};
    for (int q = t; q < 288; q += 128) {
        int m = q / 96, qq = q % 96;
        int hd = qq / 3, rr = qq % 3;
        float v = T[rr];
        #pragma unroll
        for (int c = 0; c < 3; c++) v += pr[384 + m*96 + hd*3 + c] * R[c*3 + rr];
        if (m == 0)      { g_qp[i*96 + qq] = v; pg[qq] = v; }
        else if (m == 1) { g_kpT[qq*NN + i] = v; pg[96 + qq] = v; }
        else               g_vp[i*96 + qq] = v;
    }
    __syncthreads();

    if (t < 16) {
        int m = t >> 3, h = t & 7;
        float s = 0.f;
        #pragma unroll
        for (int q = 0; q < 12; q++) { float v = pg[m*96 + h*12 + q]; s += v*v; }
        (m ? g_k2 : g_q2)[h*NN + i] = s;
    }
}

// ---------------------------------------------------------------------------
// k_fused: ONE edge pass. XOR-swizzled edge tile; 2-pass phase B (4 heads
// each) for smaller smem + registers. grid (512, 8), 256 threads, 4 blk/SM.
// ---------------------------------------------------------------------------
#define EIDX(r, c) ((r)*32 + ((c) ^ ((r) & 31)))

__global__ void __launch_bounds__(256, 4) k_fused(const float* __restrict__ edge,
                        const float* __restrict__ Wb,
                        const float* __restrict__ bb,
                        const float* __restrict__ pw) {
    int i = blockIdx.x, jc = blockIdx.y, j0 = jc * 64;
    int t = threadIdx.x; // 256

    __shared__ float4 edge_s[64*32];     // 32 KB (XOR swizzle)
    __shared__ float4 wb4[32*8];         // 4 KB
    __shared__ float lg[8*64];           // 2 KB
    __shared__ float qs_s[128], qp_s[96], q2_s[8], cw_s[8], bb_s[8];
    __shared__ __align__(16) float scratch[2560];  // 10.2 KB: pair_red / red4

    if (t < 128) qs_s[t] = g_qs[i*128 + t];
    else if (t < 224) qp_s[t-128] = g_qp[i*96 + (t-128)];
    else if (t < 232) {
        int h = t - 224;
        q2_s[h] = g_q2[h*NN + i];
        bb_s[h] = bb[h];
        cw_s[h] = 0.5f * POINT_SCALE * log1pf(__expf(pw[h]));
    }
    {
        int eg = t >> 3, h = t & 7;
        wb4[eg*8 + h] = make_float4(Wb[(eg*4+0)*8 + h], Wb[(eg*4+1)*8 + h],
                                    Wb[(eg*4+2)*8 + h], Wb[(eg*4+3)*8 + h]);
    }
    {
        const float4* eg = (const float4*)(edge + ((size_t)i*NN + j0)*EE);
        #pragma unroll 8
        for (int idx = t; idx < 2048; idx += 256) {
            int r = idx >> 5, c = idx & 31;
            edge_s[EIDX(r, c)] = eg[idx];
        }
    }
    __syncthreads();

    // ---- Phase B: two passes of 4 heads each ----
    #pragma unroll
    for (int hp = 0; hp < 2; hp++) {
        // B1: thread (jl2 = t&31, q = t>>5): g in [q*4,q*4+4), j in {jl2,jl2+32}
        {
            int jl2 = t & 31, q = t >> 5;
            float p0[4] = {0,0,0,0};
            float p1[4] = {0,0,0,0};
            #pragma unroll
            for (int gg = 0; gg < 4; gg++) {
                int g = q*4 + gg;
                float4 e0 = edge_s[EIDX(jl2, g)];
                float4 e1 = edge_s[EIDX(jl2+32, g)];
                #pragma unroll
                for (int h4 = 0; h4 < 4; h4++) {
                    float4 w = wb4[g*8 + hp*4 + h4];
                    p0[h4] += e0.x*w.x + e0.y*w.y + e0.z*w.z + e0.w*w.w;
                    p1[h4] += e1.x*w.x + e1.y*w.y + e1.z*w.z + e1.w*w.w;
                }
            }
            #pragma unroll
            for (int h4 = 0; h4 < 4; h4++) {
                scratch[(q*64 + jl2)*5 + h4]      = p0[h4];
                scratch[(q*64 + jl2 + 32)*5 + h4] = p1[h4];
            }
        }
        __syncthreads();
        // B2: thread (jl = t&63, hq = t>>6) -> head h = hp*4 + hq
        {
            int jl = t & 63, hq = t >> 6;
            int h = hp*4 + hq;
            float pb = 0.f;
            #pragma unroll
            for (int q = 0; q < 8; q++) pb += scratch[(q*64 + jl)*5 + hq];
            int j = j0 + jl;
            float s = 0.f;
            #pragma unroll
            for (int k = 0; k < 16; k++)
                s += qs_s[h*16 + k] * g_kkT[(h*16 + k)*NN + j];
            float c = 0.f;
            #pragma unroll
            for (int k = 0; k < 12; k++)
                c += qp_s[h*12 + k] * g_kpT[(h*12 + k)*NN + j];
            float d = q2_s[h] + g_k2[h*NN + j] - 2.f*c;
            lg[h*64 + jl] = SCAL_SCALE*s - cw_s[h]*d + (pb + bb_s[h])*PAIR_SCALE;
        }
        __syncthreads();
    }

    // ---- Phase C: per-head chunk stats + exp; warp w = head w ----
    {
        int w = t >> 5, lane = t & 31;
        float v0 = lg[w*64 + lane], v1 = lg[w*64 + lane + 32];
        float m = fmaxf(v0, v1);
        #pragma unroll
        for (int s = 16; s > 0; s >>= 1) m = fmaxf(m, __shfl_xor_sync(0xffffffffu, m, s));
        float e0 = __expf(v0 - m), e1 = __expf(v1 - m);
        lg[w*64 + lane]      = e0;
        lg[w*64 + lane + 32] = e1;
        float cs = e0 + e1;
        #pragma unroll
        for (int s = 16; s > 0; s >>= 1) cs += __shfl_xor_sync(0xffffffffu, cs, s);
        g_attn[((size_t)w*NN + i)*NN + j0 + lane]      = e0;
        g_attn[((size_t)w*NN + i)*NN + j0 + lane + 32] = e1;
        if (lane == 0) {
            g_mc[w*(NN*8) + i*8 + jc] = m;
            g_sc[w*(NN*8) + i*8 + jc] = cs;
        }
    }
    __syncthreads();

    // ---- Phase D: rp partial from smem tile x lg ----
    {
        float4* red4 = (float4*)scratch;
        const float4* lg4 = (const float4*)lg;
        int e4 = t & 31, hh = (t >> 5) & 1, jg = t >> 6;
        float4 acc[4];
        #pragma unroll
        for (int hl = 0; hl < 4; hl++) acc[hl] = make_float4(0.f,0.f,0.f,0.f);

        #pragma unroll
        for (int j4 = 0; j4 < 4; j4++) {
            float4 pv[4];
            #pragma unroll
            for (int hl = 0; hl < 4; hl++)
                pv[hl] = lg4[(hh*4 + hl)*16 + jg*4 + j4];
            #pragma unroll
            for (int jj = 0; jj < 4; jj++) {
                int jrow = jg*16 + j4*4 + jj;
                float4 ev = edge_s[EIDX(jrow, e4)];
                #pragma unroll
                for (int hl = 0; hl < 4; hl++) {
                    float p = (jj == 0) ? pv[hl].x : (jj == 1) ? pv[hl].y
                            : (jj == 2) ? pv[hl].z : pv[hl].w;
                    acc[hl].x += ev.x*p; acc[hl].y += ev.y*p;
                    acc[hl].z += ev.z*p; acc[hl].w += ev.w*p;
                }
            }
        }
        if (jg >= 2) {
            #pragma unroll
            for (int hl = 0; hl < 4; hl++)
                red4[(((jg-2)*2 + hh)*4 + hl)*32 + e4] = acc[hl];
        }
        __syncthreads();
        if (jg < 2) {
            #pragma unroll
            for (int hl = 0; hl < 4; hl++) {
                float4 o = red4[((jg*2 + hh)*4 + hl)*32 + e4];
                acc[hl].x += o.x; acc[hl].y += o.y; acc[hl].z += o.z; acc[hl].w += o.w;
            }
        }
        __syncthreads();
        if (jg == 1) {
            #pragma unroll
            for (int hl = 0; hl < 4; hl++)
                red4[(hh*4 + hl)*32 + e4] = acc[hl];
        }
        __syncthreads();
        if (jg == 0) {
            float4* outp = (float4*)(g_rpp + ((size_t)jc*NN + i)*1024);
            #pragma unroll
            for (int hl = 0; hl < 4; hl++) {
                float4 o = red4[(hh*4 + hl)*32 + e4];
                outp[(hh*4 + hl)*32 + e4] = make_float4(acc[hl].x+o.x, acc[hl].y+o.y,
                                                        acc[hl].z+o.z, acc[hl].w+o.w);
            }
        }
    }
}

// ---------------------------------------------------------------------------
// k_rs: rs (16) + pts (12) per head via tiled attn x V GEMM.
// ---------------------------------------------------------------------------
__global__ void __launch_bounds__(256) k_rs() {
    int i0 = blockIdx.x * 32, h = blockIdx.y;
    int t = threadIdx.x;
    __shared__ float ash[32][68];
    __shared__ float wsh[64][36];
    __shared__ float scl_s[32][8];

    int il = t >> 3, cq = t & 7;
    float acc[4] = {0.f, 0.f, 0.f, 0.f};

    if (t < 32) {
        int r = t;
        float mc[8], sc[8], m = -1e30f;
        #pragma unroll
        for (int jc = 0; jc < 8; jc++) {
            mc[jc] = g_mc[h*(NN*8) + (i0 + r)*8 + jc];
            sc[jc] = g_sc[h*(NN*8) + (i0 + r)*8 + jc];
            m = fmaxf(m, mc[jc]);
        }
        float S = 0.f;
        #pragma unroll
        for (int jc = 0; jc < 8; jc++) { float e = __expf(mc[jc] - m); mc[jc] = e; S += sc[jc]*e; }
        float inv = 1.f / S;
        #pragma unroll
        for (int jc = 0; jc < 8; jc++) scl_s[r][jc] = mc[jc] * inv;
    }
    __syncthreads();

    for (int jc = 0; jc < 8; jc++) {
        int j0 = jc * 64;
        #pragma unroll
        for (int rep = 0; rep < 2; rep++) {
            int fid = t + rep*256;
            int row = fid >> 4, cf = fid & 15;
            float4 v = *(const float4*)&g_attn[((size_t)h*NN + i0 + row)*NN + j0 + cf*4];
            float s = scl_s[row][jc];
            *(float4*)&ash[row][cf*4] = make_float4(v.x*s, v.y*s, v.z*s, v.w*s);
        }
        { int j = t >> 2, k4 = t & 3;
          float4 v = *(const float4*)&g_vs[(size_t)(j0 + j)*128 + h*16 + k4*4];
          *(float4*)&wsh[j][k4*4] = v; }
        if (t < 192) { int j = t / 3, g = t % 3;
          float4 v = *(const float4*)&g_vp[(size_t)(j0 + j)*96 + h*12 + g*4];
          *(float4*)&wsh[j][16 + g*4] = v; }
        __syncthreads();

        #pragma unroll 8
        for (int j = 0; j < 64; j++) {
            float a = ash[il][j];
            float4 wv = *(const float4*)&wsh[j][cq*4];
            acc[0] += a*wv.x; acc[1] += a*wv.y; acc[2] += a*wv.z; acc[3] += a*wv.w;
        }
        __syncthreads();
    }

    int i = i0 + il;
    #pragma unroll
    for (int b = 0; b < 4; b++) {
        int c = cq*4 + b;
        if (c < 16) g_cat[(size_t)i*CATD + h*16 + c] = acc[b];
        else if (c < 28) g_pts[i*96 + h*12 + (c - 16)] = acc[b];
    }
}

// ---------------------------------------------------------------------------
// k_cat: rp partial merge + inverse rigid + norms. grid 512, 256 threads.
// ---------------------------------------------------------------------------
__global__ void k_cat(const float* __restrict__ rot,
                      const float* __restrict__ trans) {
    int i = blockIdx.x, t = threadIdx.x;
    __shared__ float scl_s[8][8];
    __shared__ float pts_s[96];

    if (t < 8) {
        int h = t;
        float mc[8], sc[8], m = -1e30f;
        #pragma unroll
        for (int jc = 0; jc < 8; jc++) {
            mc[jc] = g_mc[h*(NN*8) + i*8 + jc];
            sc[jc] = g_sc[h*(NN*8) + i*8 + jc];
            m = fmaxf(m, mc[jc]);
        }
        float S = 0.f;
        #pragma unroll
        for (int jc = 0; jc < 8; jc++) { float e = __expf(mc[jc] - m); mc[jc] = e; S += sc[jc]*e; }
        float inv = 1.f / S;
        #pragma unroll
        for (int jc = 0; jc < 8; jc++) scl_s[h][jc] = mc[jc] * inv;
    }
    else if (t >= 32 && t < 128) pts_s[t - 32] = g_pts[i*96 + (t - 32)];
    __syncthreads();

    float* cat = &g_cat[(size_t)i*CATD];
    for (int o = t; o < 1024; o += 256) {
        int h = o >> 7;
        float s = 0.f;
        #pragma unroll
        for (int jc = 0; jc < 8; jc++)
            s += g_rpp[((size_t)jc*NN + i)*1024 + o] * scl_s[h][jc];
        cat[256 + o] = s;
    }

    if (t < 32) {
        int base = t * 3;
        float T0 = trans[i*3], T1 = trans[i*3+1], T2 = trans[i*3+2];
        float x0 = pts_s[base] - T0, x1 = pts_s[base+1] - T1, x2 = pts_s[base+2] - T2;
        const float* R = &rot[i*9];
        float l0 = x0*R[0] + x1*R[1] + x2*R[2];
        float l1 = x0*R[3] + x1*R[4] + x2*R[5];
        float l2 = x0*R[6] + x1*R[7] + x2*R[8];
        cat[128 + base]     = l0;
        cat[128 + base + 1] = l1;
        cat[128 + base + 2] = l2;
        cat[224 + t] = sqrtf(l0*l0 + l1*l1 + l2*l2 + 1e-8f);
    }
}

// ---------------------------------------------------------------------------
// GEMM: 32x64 tile, BK=32, 128 threads, 4x4 micro. Split-K via blockIdx.z.
// ---------------------------------------------------------------------------
template<int LDX, int NC>
__global__ void k_gemm64(const float* __restrict__ X, const float* __restrict__ W,
                         const float* __restrict__ bias,
                         float* __restrict__ Y0, float* __restrict__ Y1,
                         float* __restrict__ Y2, float* __restrict__ Y3, int klen) {
    int r0 = blockIdx.x * 32, c0 = blockIdx.y * 64;
    int z = blockIdx.z;
    int kbase = z * klen;
    float* Y = (z == 0) ? Y0 : (z == 1) ? Y1 : (z == 2) ? Y2 : Y3;
    int t = threadIdx.x;
    __shared__ float Xs[32][36];
    __shared__ float Ws[32][68];

    int tx = t & 15, ty = t >> 4;
    float acc[4][4];
    #pragma unroll
    for (int a = 0; a < 4; a++)
        #pragma unroll
        for (int b = 0; b < 4; b++) acc[a][b] = 0.f;

    int xrow = t >> 2, xk4 = t & 3;
    for (int kc = 0; kc < klen; kc += 32) {
        int kg = kbase + kc;
        #pragma unroll
        for (int hh = 0; hh < 2; hh++) {
            int kq = xk4*2 + hh;
            float4 v = *(const float4*)&X[(size_t)(r0 + xrow)*LDX + kg + kq*4];
            Xs[kq*4 + 0][xrow] = v.x;
            Xs[kq*4 + 1][xrow] = v.y;
            Xs[kq*4 + 2][xrow] = v.z;
            Xs[kq*4 + 3][xrow] = v.w;
        }
        #pragma unroll
        for (int it = 0; it < 4; it++) {
            int idx = t + 128*it;
            int k = idx >> 4, cf4 = idx & 15;
            float4 v = *(const float4*)&W[(size_t)(kg + k)*NC + c0 + cf4*4];
            *(float4*)&Ws[k][cf4*4] = v;
        }
        __syncthreads();

        #pragma unroll
        for (int k = 0; k < 32; k++) {
            float4 xv = *(const float4*)&Xs[k][ty*4];
            float4 wv = *(const float4*)&Ws[k][tx*4];
            acc[0][0] += xv.x*wv.x; acc[0][1] += xv.x*wv.y; acc[0][2] += xv.x*wv.z; acc[0][3] += xv.x*wv.w;
            acc[1][0] += xv.y*wv.x; acc[1][1] += xv.y*wv.y; acc[1][2] += xv.y*wv.z; acc[1][3] += xv.y*wv.w;
            acc[2][0] += xv.z*wv.x; acc[2][1] += xv.z*wv.y; acc[2][2] += xv.z*wv.z; acc[2][3] += xv.z*wv.w;
            acc[3][0] += xv.w*wv.x; acc[3][1] += xv.w*wv.y; acc[3][2] += xv.w*wv.z; acc[3][3] += xv.w*wv.w;
        }
        __syncthreads();
    }

    #pragma unroll
    for (int a = 0; a < 4; a++) {
        int row = r0 + ty*4 + a;
        #pragma unroll
        for (int b = 0; b < 4; b++) {
            int col = c0 + tx*4 + b;
            float v = acc[a][b];
            if (z == 0) v += bias[col];
            Y[(size_t)row*NC + col] = v;
        }
    }
}

// ---------------------------------------------------------------------------
// Projection GEMM with inline weight gather from the 6 source matrices.
// Y[512 x 704] = node[512 x 384] @ Wall, Wall packed virtually.
// ---------------------------------------------------------------------------
__global__ void k_gemmProj(const float* __restrict__ X,
                           const float* __restrict__ Wq_s, const float* __restrict__ Wk_s,
                           const float* __restrict__ Wv_s,
                           const float* __restrict__ Wq_p, const float* __restrict__ Wk_p,
                           const float* __restrict__ Wv_p,
                           float* __restrict__ Y) {
    int r0 = blockIdx.x * 32, c0 = blockIdx.y * 64;
    int t = threadIdx.x;
    __shared__ float Xs[32][36];
    __shared__ float Ws[32][68];

    int tx = t & 15, ty = t >> 4;
    float acc[4][4];
    #pragma unroll
    for (int a = 0; a < 4; a++)
        #pragma unroll
        for (int b = 0; b < 4; b++) acc[a][b] = 0.f;

    // per-slot weight source resolution (done once)
    const float* wsrc[4]; int wcol[4], wld[4];
    #pragma unroll
    for (int it = 0; it < 4; it++) {
        int idx = t + 128*it;
        int c = c0 + (idx & 15)*4;
        const float* src; int sc, ld;
        if (c < 128)      { src = Wq_s; sc = c;      ld = 128; }
        else if (c < 256) { src = Wk_s; sc = c-128;  ld = 128; }
        else if (c < 384) { src = Wv_s; sc = c-256;  ld = 128; }
        else if (c < 480) { src = Wq_p; sc = c-384;  ld = 96; }
        else if (c < 576) { src = Wk_p; sc = c-480;  ld = 96; }
        else if (c < 672) { src = Wv_p; sc = c-576;  ld = 96; }
        else              { src = g_zero; sc = 0;    ld = 0; }
        wsrc[it] = src; wcol[it] = sc; wld[it] = ld;
    }

    int xrow = t >> 2, xk4 = t & 3;
    for (int kg = 0; kg < DD; kg += 32) {
        #pragma unroll
        for (int hh = 0; hh < 2; hh++) {
            int kq = xk4*2 + hh;
            float4 v = *(const float4*)&X[(size_t)(r0 + xrow)*DD + kg + kq*4];
            Xs[kq*4 + 0][xrow] = v.x;
            Xs[kq*4 + 1][xrow] = v.y;
            Xs[kq*4 + 2][xrow] = v.z;
            Xs[kq*4 + 3][xrow] = v.w;
        }
        #pragma unroll
        for (int it = 0; it < 4; it++) {
            int idx = t + 128*it;
            int k = idx >> 4, cf4 = idx & 15;
            float4 v = *(const float4*)&wsrc[it][(size_t)(kg + k)*wld[it] + wcol[it]];
            *(float4*)&Ws[k][cf4*4] = v;
        }
        __syncthreads();

        #pragma unroll
        for (int k = 0; k < 32; k++) {
            float4 xv = *(const float4*)&Xs[k][ty*4];
            float4 wv = *(const float4*)&Ws[k][tx*4];
            acc[0][0] += xv.x*wv.x; acc[0][1] += xv.x*wv.y; acc[0][2] += xv.x*wv.z; acc[0][3] += xv.x*wv.w;
            acc[1][0] += xv.y*wv.x; acc[1][1] += xv.y*wv.y; acc[1][2] += xv.y*wv.z; acc[1][3] += xv.y*wv.w;
            acc[2][0] += xv.z*wv.x; acc[2][1] += xv.z*wv.y; acc[2][2] += xv.z*wv.z; acc[2][3] += xv.z*wv.w;
            acc[3][0] += xv.w*wv.x; acc[3][1] += xv.w*wv.y; acc[3][2] += xv.w*wv.z; acc[3][3] += xv.w*wv.w;
        }
        __syncthreads();
    }

    #pragma unroll
    for (int a = 0; a < 4; a++) {
        int row = r0 + ty*4 + a;
        #pragma unroll
        for (int b = 0; b < 4; b++) {
            int col = c0 + tx*4 + b;
            Y[(size_t)row*PSTR + col] = acc[a][b];
        }
    }
}

// ---------------------------------------------------------------------------
// GEMM with X = relu(X0+X1+X2+X3) fused at load. Same tiling.
// ---------------------------------------------------------------------------
template<int LDX, int NC>
__global__ void k_gemm64sum(const float* __restrict__ X0, const float* __restrict__ X1,
                            const float* __restrict__ X2, const float* __restrict__ X3,
                            const float* __restrict__ W, const float* __restrict__ bias,
                            float* __restrict__ Y0, float* __restrict__ Y1,
                            float* __restrict__ Y2, float* __restrict__ Y3, int klen) {
    int r0 = blockIdx.x * 32, c0 = blockIdx.y * 64;
    int z = blockIdx.z;
    int kbase = z * klen;
    float* Y = (z == 0) ? Y0 : (z == 1) ? Y1 : (z == 2) ? Y2 : Y3;
    int t = threadIdx.x;
    __shared__ float Xs[32][36];
    __shared__ float Ws[32][68];

    int tx = t & 15, ty = t >> 4;
    float acc[4][4];
    #pragma unroll
    for (int a = 0; a < 4; a++)
        #pragma unroll
        for (int b = 0; b < 4; b++) acc[a][b] = 0.f;

    int xrow = t >> 2, xk4 = t & 3;
    for (int kc = 0; kc < klen; kc += 32) {
        int kg = kbase + kc;
        #pragma unroll
        for (int hh = 0; hh < 2; hh++) {
            int kq = xk4*2 + hh;
            size_t off = (size_t)(r0 + xrow)*LDX + kg + kq*4;
            float4 a = *(const float4*)&X0[off];
            float4 b = *(const float4*)&X1[off];
            float4 c = *(const float4*)&X2[off];
            float4 d = *(const float4*)&X3[off];
            Xs[kq*4 + 0][xrow] = fmaxf(a.x+b.x+c.x+d.x, 0.f);
            Xs[kq*4 + 1][xrow] = fmaxf(a.y+b.y+c.y+d.y, 0.f);
            Xs[kq*4 + 2][xrow] = fmaxf(a.z+b.z+c.z+d.z, 0.f);
            Xs[kq*4 + 3][xrow] = fmaxf(a.w+b.w+c.w+d.w, 0.f);
        }
        #pragma unroll
        for (int it = 0; it < 4; it++) {
            int idx = t + 128*it;
            int k = idx >> 4, cf4 = idx & 15;
            float4 v = *(const float4*)&W[(size_t)(kg + k)*NC + c0 + cf4*4];
            *(float4*)&Ws[k][cf4*4] = v;
        }
        __syncthreads();

        #pragma unroll
        for (int k = 0; k < 32; k++) {
            float4 xv = *(const float4*)&Xs[k][ty*4];
            float4 wv = *(const float4*)&Ws[k][tx*4];
            acc[0][0] += xv.x*wv.x; acc[0][1] += xv.x*wv.y; acc[0][2] += xv.x*wv.z; acc[0][3] += xv.x*wv.w;
            acc[1][0] += xv.y*wv.x; acc[1][1] += xv.y*wv.y; acc[1][2] += xv.y*wv.z; acc[1][3] += xv.y*wv.w;
            acc[2][0] += xv.z*wv.x; acc[2][1] += xv.z*wv.y; acc[2][2] += xv.z*wv.z; acc[2][3] += xv.z*wv.w;
            acc[3][0] += xv.w*wv.x; acc[3][1] += xv.w*wv.y; acc[3][2] += xv.w*wv.z; acc[3][3] += xv.w*wv.w;
        }
        __syncthreads();
    }

    #pragma unroll
    for (int a = 0; a < 4; a++) {
        int row = r0 + ty*4 + a;
        #pragma unroll
        for (int b = 0; b < 4; b++) {
            int col = c0 + tx*4 + b;
            float v = acc[a][b];
            if (z == 0) v += bias[col];
            Y[(size_t)row*NC + col] = v;
        }
    }
}

// ---------------------------------------------------------------------------
// LayerNorm over 384 of (a+b+c+d). 128 threads, 3 elems each.
// ---------------------------------------------------------------------------
__global__ void k_ln4(const float* __restrict__ ia, const float* __restrict__ ib,
                      const float* __restrict__ ic, const float* __restrict__ id,
                      const float* __restrict__ g, const float* __restrict__ b,
                      float* __restrict__ out) {
    int i = blockIdx.x, t = threadIdx.x;
    __shared__ float red[128];
    float v0 = ia[i*DD+t]     + ib[i*DD+t]     + ic[i*DD+t]     + id[i*DD+t];
    float v1 = ia[i*DD+t+128] + ib[i*DD+t+128] + ic[i*DD+t+128] + id[i*DD+t+128];
    float v2 = ia[i*DD+t+256] + ib[i*DD+t+256] + ic[i*DD+t+256] + id[i*DD+t+256];
    red[t] = v0 + v1 + v2;
    __syncthreads();
    #pragma unroll
    for (int s = 64; s > 0; s >>= 1) { if (t < s) red[t] += red[t+s]; __syncthreads(); }
    float mu = red[0] * (1.f/384.f);
    __syncthreads();
    float d0 = v0-mu, d1 = v1-mu, d2 = v2-mu;
    red[t] = d0*d0 + d1*d1 + d2*d2;
    __syncthreads();
    #pragma unroll
    for (int s = 64; s > 0; s >>= 1) { if (t < s) red[t] += red[t+s]; __syncthreads(); }
    float inv = rsqrtf(red[0] * (1.f/384.f) + 1e-5f);
    out[i*DD + t]       = d0*inv*g[t]       + b[t];
    out[i*DD + t + 128] = d1*inv*g[t+128]   + b[t+128];
    out[i*DD + t + 256] = d2*inv*g[t+256]   + b[t+256];
}

// ---------------------------------------------------------------------------
extern "C" void kernel_launch(void* const* d_in, const int* in_sizes, int n_in,
                              void* d_out, int out_size) {
    const float* node  = (const float*)d_in[0];
    const float* edge  = (const float*)d_in[1];
    const float* rot   = (const float*)d_in[2];
    const float* trans = (const float*)d_in[3];
    const float* Wq_s = (const float*)d_in[5];
    const float* Wk_s = (const float*)d_in[6];
    const float* Wv_s = (const float*)d_in[7];
    const float* Wq_p = (const float*)d_in[8];
    const float* Wk_p = (const float*)d_in[9];
    const float* Wv_p = (const float*)d_in[10];
    const float* pw   = (const float*)d_in[11];
    const float* Wb   = (const float*)d_in[12];
    const float* bb   = (const float*)d_in[13];
    const float* Wo   = (const float*)d_in[14];
    const float* bo   = (const float*)d_in[15];
    const float* g1   = (const float*)d_in[16];
    const float* beta1= (const float*)d_in[17];
    const float* W1   = (const float*)d_in[18];
    const float* b1   = (const float*)d_in[19];
    const float* W2   = (const float*)d_in[20];
    const float* b2   = (const float*)d_in[21];
    const float* W3   = (const float*)d_in[22];
    const float* b3   = (const float*)d_in[23];
    const float* g2   = (const float*)d_in[24];
    const float* beta2= (const float*)d_in[25];
    float* out = (float*)d_out;

    float *p_cat, *p_t0, *p_t1, *p_t2, *p_t3, *p_x1;
    float *p_u0, *p_u1, *p_u2, *p_u3, *p_v0, *p_v1, *p_v2, *p_v3;
    float *p_proj;
    cudaGetSymbolAddress((void**)&p_cat, g_cat);
    cudaGetSymbolAddress((void**)&p_t0, g_t0);
    cudaGetSymbolAddress((void**)&p_t1, g_t1);
    cudaGetSymbolAddress((void**)&p_t2, g_t2);
    cudaGetSymbolAddress((void**)&p_t3, g_t3);
    cudaGetSymbolAddress((void**)&p_u0, g_u0);
    cudaGetSymbolAddress((void**)&p_u1, g_u1);
    cudaGetSymbolAddress((void**)&p_u2, g_u2);
    cudaGetSymbolAddress((void**)&p_u3, g_u3);
    cudaGetSymbolAddress((void**)&p_v0, g_v0);
    cudaGetSymbolAddress((void**)&p_v1, g_v1);
    cudaGetSymbolAddress((void**)&p_v2, g_v2);
    cudaGetSymbolAddress((void**)&p_v3, g_v3);
    cudaGetSymbolAddress((void**)&p_x1, g_x1);
    cudaGetSymbolAddress((void**)&p_proj, g_proj);

    // 1: proj GEMM with inline weight gather
    k_gemmProj<<<dim3(16, 11), 128>>>(node, Wq_s, Wk_s, Wv_s, Wq_p, Wk_p, Wv_p, p_proj);
    // 2: scatter + rigid + norms
    k_post<<<NN, 128>>>(rot, trans);
    // 3: fused attention (single edge pass)
    k_fused<<<dim3(NN, 8), 256>>>(edge, Wb, bb, pw);
    // 4: rs/pts  <-- profiled slot
    k_rs<<<dim3(16, 8), 256>>>();
    k_cat<<<NN, 256>>>(rot, trans);

    // Wo: split-K 4 x 320 -> LN
    k_gemm64<CATD, DD><<<dim3(16, 6, 4), 128>>>(p_cat, Wo, bo, p_t0, p_t1, p_t2, p_t3, 320);
    k_ln4<<<NN, 128>>>(p_t0, p_t1, p_t2, p_t3, g1, beta1, p_x1);
    // W1: split-K 4 x 96 -> partials u
    k_gemm64<DD, HID><<<dim3(16, 12, 4), 128>>>(p_x1, W1, b1, p_u0, p_u1, p_u2, p_u3, 96);
    // W2: X = relu(sum u); split-K 4 x 192 -> partials v
    k_gemm64sum<HID, HID><<<dim3(16, 12, 4), 128>>>(p_u0, p_u1, p_u2, p_u3, W2, b2,
                                                    p_v0, p_v1, p_v2, p_v3, 192);
    // W3: X = relu(sum v); split-K 4 x 192 -> LN
    k_gemm64sum<HID, DD><<<dim3(16, 6, 4), 128>>>(p_v0, p_v1, p_v2, p_v3, W3, b3,
                                                  p_t0, p_t1, p_t2, p_t3, 192);
    k_ln4<<<NN, 128>>>(p_t0, p_t1, p_t2, p_t3, g2, beta2, out);
}

// round 17
// speedup vs baseline: 1.0565x; 1.0565x over previous
#include <cuda_runtime.h>
#include <cuda_bf16.h>
#include <math.h>

#define NN 512
#define DD 384
#define EE 128
#define HH 8
#define CATD 1280
#define HID 768
#define PSTR 704

static __device__ __constant__ float SCAL_SCALE = 0.14433756729740643f; // (3*16)^-0.5
static __device__ __constant__ float POINT_SCALE = 0.13608276348795434f; // (3*4*4.5)^-0.5
static __device__ __constant__ float PAIR_SCALE = 0.5773502691896258f;  // 3^-0.5

// scratch
__device__ float g_zero[PSTR];               // static zero (never written)
__device__ float g_proj[NN*PSTR];
__device__ float g_qs[NN*128];
__device__ float g_kkT[128*NN];   // [h*16+k][j]
__device__ float g_vs[NN*128];
__device__ float g_qp[NN*96];
__device__ float g_kpT[96*NN];    // [h*12+q][j]
__device__ float g_vp[NN*96];
__device__ float g_q2[HH*NN];
__device__ float g_k2[HH*NN];
__device__ float g_attn[(size_t)HH*NN*NN];   // exp(raw - m_chunk)
__device__ float g_mc[HH*NN*8];
__device__ float g_sc[HH*NN*8];
__device__ float g_rsp[(size_t)4*NN*224];    // rs/pts partials [z][i][h*28+c]
__device__ float g_rpp[(size_t)8*NN*1024];
__device__ float g_cat[(size_t)NN*CATD];
__device__ float g_t0[NN*DD];
__device__ float g_t1[NN*DD];
__device__ float g_t2[NN*DD];
__device__ float g_t3[NN*DD];
__device__ float g_u0[NN*HID];
__device__ float g_u1[NN*HID];
__device__ float g_u2[NN*HID];
__device__ float g_u3[NN*HID];
__device__ float g_v0[NN*HID];
__device__ float g_v1[NN*HID];
__device__ float g_v2[NN*HID];
__device__ float g_v3[NN*HID];
__device__ float g_x1[NN*DD];

// ---------------------------------------------------------------------------
// K_post: scatter proj results, rigid transforms, q2/k2. One block per i.
// ---------------------------------------------------------------------------
__global__ void k_post(const float* __restrict__ rot,
                       const float* __restrict__ trans) {
    int i = blockIdx.x, t = threadIdx.x; // 128
    __shared__ float pg[192];
    const float* pr = &g_proj[i*PSTR];

    float a = pr[t];
    g_qs[i*128 + t] = a;
    g_kkT[t*NN + i] = pr[128 + t];
    g_vs[i*128 + t] = pr[256 + t];

    const float* R = &rot[i*9];
    float T[3] = {trans[i*3], trans[i*3+1], trans[i*3+2]};
    for (int q = t; q < 288; q += 128) {
        int m = q / 96, qq = q % 96;
        int hd = qq / 3, rr = qq % 3;
        float v = T[rr];
        #pragma unroll
        for (int c = 0; c < 3; c++) v += pr[384 + m*96 + hd*3 + c] * R[c*3 + rr];
        if (m == 0)      { g_qp[i*96 + qq] = v; pg[qq] = v; }
        else if (m == 1) { g_kpT[qq*NN + i] = v; pg[96 + qq] = v; }
        else               g_vp[i*96 + qq] = v;
    }
    __syncthreads();

    if (t < 16) {
        int m = t >> 3, h = t & 7;
        float s = 0.f;
        #pragma unroll
        for (int q = 0; q < 12; q++) { float v = pg[m*96 + h*12 + q]; s += v*v; }
        (m ? g_k2 : g_q2)[h*NN + i] = s;
    }
}

// ---------------------------------------------------------------------------
// k_fused (R15 known-good): ONE edge pass per (i, 64-j chunk).
// ---------------------------------------------------------------------------
__global__ void __launch_bounds__(256) k_fused(const float* __restrict__ edge,
                        const float* __restrict__ Wb,
                        const float* __restrict__ bb,
                        const float* __restrict__ pw) {
    int i = blockIdx.x, jc = blockIdx.y, j0 = jc * 64;
    int t = threadIdx.x; // 256

    __shared__ float4 edge_s[64*33];     // 33.8 KB
    __shared__ float4 wb4[32*8];         // 4 KB
    __shared__ float lg[8*64];           // 2 KB
    __shared__ float qs_s[128], qp_s[96], q2_s[8], cw_s[8], bb_s[8];
    __shared__ float scratch[4608];      // 18.4 KB

    if (t < 128) qs_s[t] = g_qs[i*128 + t];
    else if (t < 224) qp_s[t-128] = g_qp[i*96 + (t-128)];
    else if (t < 232) {
        int h = t - 224;
        q2_s[h] = g_q2[h*NN + i];
        bb_s[h] = bb[h];
        cw_s[h] = 0.5f * POINT_SCALE * log1pf(__expf(pw[h]));
    }
    {
        int eg = t >> 3, h = t & 7;
        wb4[eg*8 + h] = make_float4(Wb[(eg*4+0)*8 + h], Wb[(eg*4+1)*8 + h],
                                    Wb[(eg*4+2)*8 + h], Wb[(eg*4+3)*8 + h]);
    }
    {
        const float4* eg = (const float4*)(edge + ((size_t)i*NN + j0)*EE);
        #pragma unroll 8
        for (int idx = t; idx < 2048; idx += 256)
            edge_s[(idx >> 5)*33 + (idx & 31)] = eg[idx];
    }
    __syncthreads();

    // ---- Phase B1 ----
    {
        int jl2 = t & 31, q = t >> 5;
        float p0[8] = {0,0,0,0,0,0,0,0};
        float p1[8] = {0,0,0,0,0,0,0,0};
        #pragma unroll
        for (int gg = 0; gg < 4; gg++) {
            int g = q*4 + gg;
            float4 e0 = edge_s[jl2*33 + g];
            float4 e1 = edge_s[(jl2+32)*33 + g];
            #pragma unroll
            for (int h = 0; h < 8; h++) {
                float4 w = wb4[g*8 + h];
                p0[h] += e0.x*w.x + e0.y*w.y + e0.z*w.z + e0.w*w.w;
                p1[h] += e1.x*w.x + e1.y*w.y + e1.z*w.z + e1.w*w.w;
            }
        }
        #pragma unroll
        for (int h = 0; h < 8; h++) {
            scratch[(q*64 + jl2)*9 + h]      = p0[h];
            scratch[(q*64 + jl2 + 32)*9 + h] = p1[h];
        }
    }
    __syncthreads();

    // ---- Phase B2 ----
    {
        int jl = t & 63, hq = t >> 6;
        int hA = hq, hB = hq + 4;
        float pA = 0.f, pB = 0.f;
        #pragma unroll
        for (int q = 0; q < 8; q++) {
            pA += scratch[(q*64 + jl)*9 + hA];
            pB += scratch[(q*64 + jl)*9 + hB];
        }
        int j = j0 + jl;
        float sA = 0.f, sB = 0.f;
        #pragma unroll
        for (int k = 0; k < 16; k++) {
            sA += qs_s[hA*16 + k] * g_kkT[(hA*16 + k)*NN + j];
            sB += qs_s[hB*16 + k] * g_kkT[(hB*16 + k)*NN + j];
        }
        float cA = 0.f, cB = 0.f;
        #pragma unroll
        for (int k = 0; k < 12; k++) {
            cA += qp_s[hA*12 + k] * g_kpT[(hA*12 + k)*NN + j];
            cB += qp_s[hB*12 + k] * g_kpT[(hB*12 + k)*NN + j];
        }
        float dA = q2_s[hA] + g_k2[hA*NN + j] - 2.f*cA;
        float dB = q2_s[hB] + g_k2[hB*NN + j] - 2.f*cB;
        lg[hA*64 + jl] = SCAL_SCALE*sA - cw_s[hA]*dA + (pA + bb_s[hA])*PAIR_SCALE;
        lg[hB*64 + jl] = SCAL_SCALE*sB - cw_s[hB]*dB + (pB + bb_s[hB])*PAIR_SCALE;
    }
    __syncthreads();

    // ---- Phase C ----
    {
        int w = t >> 5, lane = t & 31;
        float v0 = lg[w*64 + lane], v1 = lg[w*64 + lane + 32];
        float m = fmaxf(v0, v1);
        #pragma unroll
        for (int s = 16; s > 0; s >>= 1) m = fmaxf(m, __shfl_xor_sync(0xffffffffu, m, s));
        float e0 = __expf(v0 - m), e1 = __expf(v1 - m);
        lg[w*64 + lane]      = e0;
        lg[w*64 + lane + 32] = e1;
        float cs = e0 + e1;
        #pragma unroll
        for (int s = 16; s > 0; s >>= 1) cs += __shfl_xor_sync(0xffffffffu, cs, s);
        g_attn[((size_t)w*NN + i)*NN + j0 + lane]      = e0;
        g_attn[((size_t)w*NN + i)*NN + j0 + lane + 32] = e1;
        if (lane == 0) {
            g_mc[w*(NN*8) + i*8 + jc] = m;
            g_sc[w*(NN*8) + i*8 + jc] = cs;
        }
    }
    __syncthreads();

    // ---- Phase D ----
    {
        float4* red4 = (float4*)scratch;
        const float4* lg4 = (const float4*)lg;
        int e4 = t & 31, hh = (t >> 5) & 1, jg = t >> 6;
        float4 acc[4];
        #pragma unroll
        for (int hl = 0; hl < 4; hl++) acc[hl] = make_float4(0.f,0.f,0.f,0.f);

        #pragma unroll
        for (int j4 = 0; j4 < 4; j4++) {
            float4 pv[4];
            #pragma unroll
            for (int hl = 0; hl < 4; hl++)
                pv[hl] = lg4[(hh*4 + hl)*16 + jg*4 + j4];
            #pragma unroll
            for (int jj = 0; jj < 4; jj++) {
                int jrow = jg*16 + j4*4 + jj;
                float4 ev = edge_s[jrow*33 + e4];
                #pragma unroll
                for (int hl = 0; hl < 4; hl++) {
                    float p = (jj == 0) ? pv[hl].x : (jj == 1) ? pv[hl].y
                            : (jj == 2) ? pv[hl].z : pv[hl].w;
                    acc[hl].x += ev.x*p; acc[hl].y += ev.y*p;
                    acc[hl].z += ev.z*p; acc[hl].w += ev.w*p;
                }
            }
        }
        if (jg >= 2) {
            #pragma unroll
            for (int hl = 0; hl < 4; hl++)
                red4[(((jg-2)*2 + hh)*4 + hl)*32 + e4] = acc[hl];
        }
        __syncthreads();
        if (jg < 2) {
            #pragma unroll
            for (int hl = 0; hl < 4; hl++) {
                float4 o = red4[((jg*2 + hh)*4 + hl)*32 + e4];
                acc[hl].x += o.x; acc[hl].y += o.y; acc[hl].z += o.z; acc[hl].w += o.w;
            }
        }
        __syncthreads();
        if (jg == 1) {
            #pragma unroll
            for (int hl = 0; hl < 4; hl++)
                red4[(hh*4 + hl)*32 + e4] = acc[hl];
        }
        __syncthreads();
        if (jg == 0) {
            float4* outp = (float4*)(g_rpp + ((size_t)jc*NN + i)*1024);
            #pragma unroll
            for (int hl = 0; hl < 4; hl++) {
                float4 o = red4[(hh*4 + hl)*32 + e4];
                outp[(hh*4 + hl)*32 + e4] = make_float4(acc[hl].x+o.x, acc[hl].y+o.y,
                                                        acc[hl].z+o.z, acc[hl].w+o.w);
            }
        }
    }
}

// ---------------------------------------------------------------------------
// k_rs: rs (16) + pts (12) per head, split-K over j-chunks.
// grid (16 i-tiles, 8 heads, 4 z), 256 threads. Each z handles 2 chunks.
// ---------------------------------------------------------------------------
__global__ void __launch_bounds__(256) k_rs() {
    int i0 = blockIdx.x * 32, h = blockIdx.y, z = blockIdx.z;
    int t = threadIdx.x;
    __shared__ float ash[32][68];
    __shared__ float wsh[64][36];
    __shared__ float scl_s[32][8];

    int il = t >> 3, cq = t & 7;
    float acc[4] = {0.f, 0.f, 0.f, 0.f};

    if (t < 32) {
        int r = t;
        float mc[8], sc[8], m = -1e30f;
        #pragma unroll
        for (int jc = 0; jc < 8; jc++) {
            mc[jc] = g_mc[h*(NN*8) + (i0 + r)*8 + jc];
            sc[jc] = g_sc[h*(NN*8) + (i0 + r)*8 + jc];
            m = fmaxf(m, mc[jc]);
        }
        float S = 0.f;
        #pragma unroll
        for (int jc = 0; jc < 8; jc++) { float e = __expf(mc[jc] - m); mc[jc] = e; S += sc[jc]*e; }
        float inv = 1.f / S;
        #pragma unroll
        for (int jc = 0; jc < 8; jc++) scl_s[r][jc] = mc[jc] * inv;
    }
    __syncthreads();

    #pragma unroll
    for (int jj = 0; jj < 2; jj++) {
        int jc = z*2 + jj;
        int j0 = jc * 64;
        #pragma unroll
        for (int rep = 0; rep < 2; rep++) {
            int fid = t + rep*256;
            int row = fid >> 4, cf = fid & 15;
            float4 v = *(const float4*)&g_attn[((size_t)h*NN + i0 + row)*NN + j0 + cf*4];
            float s = scl_s[row][jc];
            *(float4*)&ash[row][cf*4] = make_float4(v.x*s, v.y*s, v.z*s, v.w*s);
        }
        { int j = t >> 2, k4 = t & 3;
          float4 v = *(const float4*)&g_vs[(size_t)(j0 + j)*128 + h*16 + k4*4];
          *(float4*)&wsh[j][k4*4] = v; }
        if (t < 192) { int j = t / 3, g = t % 3;
          float4 v = *(const float4*)&g_vp[(size_t)(j0 + j)*96 + h*12 + g*4];
          *(float4*)&wsh[j][16 + g*4] = v; }
        __syncthreads();

        #pragma unroll 8
        for (int j = 0; j < 64; j++) {
            float a = ash[il][j];
            float4 wv = *(const float4*)&wsh[j][cq*4];
            acc[0] += a*wv.x; acc[1] += a*wv.y; acc[2] += a*wv.z; acc[3] += a*wv.w;
        }
        __syncthreads();
    }

    int i = i0 + il;
    #pragma unroll
    for (int b = 0; b < 4; b++) {
        int c = cq*4 + b;
        if (c < 28)
            g_rsp[((size_t)z*NN + i)*224 + h*28 + c] = acc[b];
    }
}

// ---------------------------------------------------------------------------
// k_cat: rs/pts partial merge + rp partial merge + inverse rigid + norms.
// ---------------------------------------------------------------------------
__global__ void k_cat(const float* __restrict__ rot,
                      const float* __restrict__ trans) {
    int i = blockIdx.x, t = threadIdx.x;
    __shared__ float scl_s[8][8];
    __shared__ float pts_s[96];

    if (t < 8) {
        int h = t;
        float mc[8], sc[8], m = -1e30f;
        #pragma unroll
        for (int jc = 0; jc < 8; jc++) {
            mc[jc] = g_mc[h*(NN*8) + i*8 + jc];
            sc[jc] = g_sc[h*(NN*8) + i*8 + jc];
            m = fmaxf(m, mc[jc]);
        }
        float S = 0.f;
        #pragma unroll
        for (int jc = 0; jc < 8; jc++) { float e = __expf(mc[jc] - m); mc[jc] = e; S += sc[jc]*e; }
        float inv = 1.f / S;
        #pragma unroll
        for (int jc = 0; jc < 8; jc++) scl_s[h][jc] = mc[jc] * inv;
    }
    __syncthreads();

    float* cat = &g_cat[(size_t)i*CATD];

    // rs/pts merge: 224 outputs
    if (t < 224) {
        float s = g_rsp[((size_t)0*NN + i)*224 + t]
                + g_rsp[((size_t)1*NN + i)*224 + t]
                + g_rsp[((size_t)2*NN + i)*224 + t]
                + g_rsp[((size_t)3*NN + i)*224 + t];
        int h = t / 28, c = t % 28;
        if (c < 16) cat[h*16 + c] = s;
        else        pts_s[h*12 + (c - 16)] = s;
    }

    // rp merge: 1024 outputs
    for (int o = t; o < 1024; o += 256) {
        int h = o >> 7;
        float s = 0.f;
        #pragma unroll
        for (int jc = 0; jc < 8; jc++)
            s += g_rpp[((size_t)jc*NN + i)*1024 + o] * scl_s[h][jc];
        cat[256 + o] = s;
    }
    __syncthreads();

    if (t < 32) {
        int base = t * 3;
        float T0 = trans[i*3], T1 = trans[i*3+1], T2 = trans[i*3+2];
        float x0 = pts_s[base] - T0, x1 = pts_s[base+1] - T1, x2 = pts_s[base+2] - T2;
        const float* R = &rot[i*9];
        float l0 = x0*R[0] + x1*R[1] + x2*R[2];
        float l1 = x0*R[3] + x1*R[4] + x2*R[5];
        float l2 = x0*R[6] + x1*R[7] + x2*R[8];
        cat[128 + base]     = l0;
        cat[128 + base + 1] = l1;
        cat[128 + base + 2] = l2;
        cat[224 + t] = sqrtf(l0*l0 + l1*l1 + l2*l2 + 1e-8f);
    }
}

// ---------------------------------------------------------------------------
// GEMM: 32x64 tile, BK=32, 128 threads, 4x4 micro. Split-K via blockIdx.z.
// ---------------------------------------------------------------------------
template<int LDX, int NC>
__global__ void k_gemm64(const float* __restrict__ X, const float* __restrict__ W,
                         const float* __restrict__ bias,
                         float* __restrict__ Y0, float* __restrict__ Y1,
                         float* __restrict__ Y2, float* __restrict__ Y3, int klen) {
    int r0 = blockIdx.x * 32, c0 = blockIdx.y * 64;
    int z = blockIdx.z;
    int kbase = z * klen;
    float* Y = (z == 0) ? Y0 : (z == 1) ? Y1 : (z == 2) ? Y2 : Y3;
    int t = threadIdx.x;
    __shared__ float Xs[32][36];
    __shared__ float Ws[32][68];

    int tx = t & 15, ty = t >> 4;
    float acc[4][4];
    #pragma unroll
    for (int a = 0; a < 4; a++)
        #pragma unroll
        for (int b = 0; b < 4; b++) acc[a][b] = 0.f;

    int xrow = t >> 2, xk4 = t & 3;
    for (int kc = 0; kc < klen; kc += 32) {
        int kg = kbase + kc;
        #pragma unroll
        for (int hh = 0; hh < 2; hh++) {
            int kq = xk4*2 + hh;
            float4 v = *(const float4*)&X[(size_t)(r0 + xrow)*LDX + kg + kq*4];
            Xs[kq*4 + 0][xrow] = v.x;
            Xs[kq*4 + 1][xrow] = v.y;
            Xs[kq*4 + 2][xrow] = v.z;
            Xs[kq*4 + 3][xrow] = v.w;
        }
        #pragma unroll
        for (int it = 0; it < 4; it++) {
            int idx = t + 128*it;
            int k = idx >> 4, cf4 = idx & 15;
            float4 v = *(const float4*)&W[(size_t)(kg + k)*NC + c0 + cf4*4];
            *(float4*)&Ws[k][cf4*4] = v;
        }
        __syncthreads();

        #pragma unroll
        for (int k = 0; k < 32; k++) {
            float4 xv = *(const float4*)&Xs[k][ty*4];
            float4 wv = *(const float4*)&Ws[k][tx*4];
            acc[0][0] += xv.x*wv.x; acc[0][1] += xv.x*wv.y; acc[0][2] += xv.x*wv.z; acc[0][3] += xv.x*wv.w;
            acc[1][0] += xv.y*wv.x; acc[1][1] += xv.y*wv.y; acc[1][2] += xv.y*wv.z; acc[1][3] += xv.y*wv.w;
            acc[2][0] += xv.z*wv.x; acc[2][1] += xv.z*wv.y; acc[2][2] += xv.z*wv.z; acc[2][3] += xv.z*wv.w;
            acc[3][0] += xv.w*wv.x; acc[3][1] += xv.w*wv.y; acc[3][2] += xv.w*wv.z; acc[3][3] += xv.w*wv.w;
        }
        __syncthreads();
    }

    #pragma unroll
    for (int a = 0; a < 4; a++) {
        int row = r0 + ty*4 + a;
        #pragma unroll
        for (int b = 0; b < 4; b++) {
            int col = c0 + tx*4 + b;
            float v = acc[a][b];
            if (z == 0) v += bias[col];
            Y[(size_t)row*NC + col] = v;
        }
    }
}

// ---------------------------------------------------------------------------
// Projection GEMM with inline weight gather from the 6 source matrices.
// ---------------------------------------------------------------------------
__global__ void k_gemmProj(const float* __restrict__ X,
                           const float* __restrict__ Wq_s, const float* __restrict__ Wk_s,
                           const float* __restrict__ Wv_s,
                           const float* __restrict__ Wq_p, const float* __restrict__ Wk_p,
                           const float* __restrict__ Wv_p,
                           float* __restrict__ Y) {
    int r0 = blockIdx.x * 32, c0 = blockIdx.y * 64;
    int t = threadIdx.x;
    __shared__ float Xs[32][36];
    __shared__ float Ws[32][68];

    int tx = t & 15, ty = t >> 4;
    float acc[4][4];
    #pragma unroll
    for (int a = 0; a < 4; a++)
        #pragma unroll
        for (int b = 0; b < 4; b++) acc[a][b] = 0.f;

    const float* wsrc[4]; int wcol[4], wld[4];
    #pragma unroll
    for (int it = 0; it < 4; it++) {
        int idx = t + 128*it;
        int c = c0 + (idx & 15)*4;
        const float* src; int sc, ld;
        if (c < 128)      { src = Wq_s; sc = c;      ld = 128; }
        else if (c < 256) { src = Wk_s; sc = c-128;  ld = 128; }
        else if (c < 384) { src = Wv_s; sc = c-256;  ld = 128; }
        else if (c < 480) { src = Wq_p; sc = c-384;  ld = 96; }
        else if (c < 576) { src = Wk_p; sc = c-480;  ld = 96; }
        else if (c < 672) { src = Wv_p; sc = c-576;  ld = 96; }
        else              { src = g_zero; sc = 0;    ld = 0; }
        wsrc[it] = src; wcol[it] = sc; wld[it] = ld;
    }

    int xrow = t >> 2, xk4 = t & 3;
    for (int kg = 0; kg < DD; kg += 32) {
        #pragma unroll
        for (int hh = 0; hh < 2; hh++) {
            int kq = xk4*2 + hh;
            float4 v = *(const float4*)&X[(size_t)(r0 + xrow)*DD + kg + kq*4];
            Xs[kq*4 + 0][xrow] = v.x;
            Xs[kq*4 + 1][xrow] = v.y;
            Xs[kq*4 + 2][xrow] = v.z;
            Xs[kq*4 + 3][xrow] = v.w;
        }
        #pragma unroll
        for (int it = 0; it < 4; it++) {
            int idx = t + 128*it;
            int k = idx >> 4, cf4 = idx & 15;
            float4 v = *(const float4*)&wsrc[it][(size_t)(kg + k)*wld[it] + wcol[it]];
            *(float4*)&Ws[k][cf4*4] = v;
        }
        __syncthreads();

        #pragma unroll
        for (int k = 0; k < 32; k++) {
            float4 xv = *(const float4*)&Xs[k][ty*4];
            float4 wv = *(const float4*)&Ws[k][tx*4];
            acc[0][0] += xv.x*wv.x; acc[0][1] += xv.x*wv.y; acc[0][2] += xv.x*wv.z; acc[0][3] += xv.x*wv.w;
            acc[1][0] += xv.y*wv.x; acc[1][1] += xv.y*wv.y; acc[1][2] += xv.y*wv.z; acc[1][3] += xv.y*wv.w;
            acc[2][0] += xv.z*wv.x; acc[2][1] += xv.z*wv.y; acc[2][2] += xv.z*wv.z; acc[2][3] += xv.z*wv.w;
            acc[3][0] += xv.w*wv.x; acc[3][1] += xv.w*wv.y; acc[3][2] += xv.w*wv.z; acc[3][3] += xv.w*wv.w;
        }
        __syncthreads();
    }

    #pragma unroll
    for (int a = 0; a < 4; a++) {
        int row = r0 + ty*4 + a;
        #pragma unroll
        for (int b = 0; b < 4; b++) {
            int col = c0 + tx*4 + b;
            Y[(size_t)row*PSTR + col] = acc[a][b];
        }
    }
}

// ---------------------------------------------------------------------------
// GEMM with X = relu(X0+X1+X2+X3) fused at load.
// ---------------------------------------------------------------------------
template<int LDX, int NC>
__global__ void k_gemm64sum(const float* __restrict__ X0, const float* __restrict__ X1,
                            const float* __restrict__ X2, const float* __restrict__ X3,
                            const float* __restrict__ W, const float* __restrict__ bias,
                            float* __restrict__ Y0, float* __restrict__ Y1,
                            float* __restrict__ Y2, float* __restrict__ Y3, int klen) {
    int r0 = blockIdx.x * 32, c0 = blockIdx.y * 64;
    int z = blockIdx.z;
    int kbase = z * klen;
    float* Y = (z == 0) ? Y0 : (z == 1) ? Y1 : (z == 2) ? Y2 : Y3;
    int t = threadIdx.x;
    __shared__ float Xs[32][36];
    __shared__ float Ws[32][68];

    int tx = t & 15, ty = t >> 4;
    float acc[4][4];
    #pragma unroll
    for (int a = 0; a < 4; a++)
        #pragma unroll
        for (int b = 0; b < 4; b++) acc[a][b] = 0.f;

    int xrow = t >> 2, xk4 = t & 3;
    for (int kc = 0; kc < klen; kc += 32) {
        int kg = kbase + kc;
        #pragma unroll
        for (int hh = 0; hh < 2; hh++) {
            int kq = xk4*2 + hh;
            size_t off = (size_t)(r0 + xrow)*LDX + kg + kq*4;
            float4 a = *(const float4*)&X0[off];
            float4 b = *(const float4*)&X1[off];
            float4 c = *(const float4*)&X2[off];
            float4 d = *(const float4*)&X3[off];
            Xs[kq*4 + 0][xrow] = fmaxf(a.x+b.x+c.x+d.x, 0.f);
            Xs[kq*4 + 1][xrow] = fmaxf(a.y+b.y+c.y+d.y, 0.f);
            Xs[kq*4 + 2][xrow] = fmaxf(a.z+b.z+c.z+d.z, 0.f);
            Xs[kq*4 + 3][xrow] = fmaxf(a.w+b.w+c.w+d.w, 0.f);
        }
        #pragma unroll
        for (int it = 0; it < 4; it++) {
            int idx = t + 128*it;
            int k = idx >> 4, cf4 = idx & 15;
            float4 v = *(const float4*)&W[(size_t)(kg + k)*NC + c0 + cf4*4];
            *(float4*)&Ws[k][cf4*4] = v;
        }
        __syncthreads();

        #pragma unroll
        for (int k = 0; k < 32; k++) {
            float4 xv = *(const float4*)&Xs[k][ty*4];
            float4 wv = *(const float4*)&Ws[k][tx*4];
            acc[0][0] += xv.x*wv.x; acc[0][1] += xv.x*wv.y; acc[0][2] += xv.x*wv.z; acc[0][3] += xv.x*wv.w;
            acc[1][0] += xv.y*wv.x; acc[1][1] += xv.y*wv.y; acc[1][2] += xv.y*wv.z; acc[1][3] += xv.y*wv.w;
            acc[2][0] += xv.z*wv.x; acc[2][1] += xv.z*wv.y; acc[2][2] += xv.z*wv.z; acc[2][3] += xv.z*wv.w;
            acc[3][0] += xv.w*wv.x; acc[3][1] += xv.w*wv.y; acc[3][2] += xv.w*wv.z; acc[3][3] += xv.w*wv.w;
        }
        __syncthreads();
    }

    #pragma unroll
    for (int a = 0; a < 4; a++) {
        int row = r0 + ty*4 + a;
        #pragma unroll
        for (int b = 0; b < 4; b++) {
            int col = c0 + tx*4 + b;
            float v = acc[a][b];
            if (z == 0) v += bias[col];
            Y[(size_t)row*NC + col] = v;
        }
    }
}

// ---------------------------------------------------------------------------
// LayerNorm over 384 of (a+b+c+d). 128 threads, 3 elems each.
// ---------------------------------------------------------------------------
__global__ void k_ln4(const float* __restrict__ ia, const float* __restrict__ ib,
                      const float* __restrict__ ic, const float* __restrict__ id,
                      const float* __restrict__ g, const float* __restrict__ b,
                      float* __restrict__ out) {
    int i = blockIdx.x, t = threadIdx.x;
    __shared__ float red[128];
    float v0 = ia[i*DD+t]     + ib[i*DD+t]     + ic[i*DD+t]     + id[i*DD+t];
    float v1 = ia[i*DD+t+128] + ib[i*DD+t+128] + ic[i*DD+t+128] + id[i*DD+t+128];
    float v2 = ia[i*DD+t+256] + ib[i*DD+t+256] + ic[i*DD+t+256] + id[i*DD+t+256];
    red[t] = v0 + v1 + v2;
    __syncthreads();
    #pragma unroll
    for (int s = 64; s > 0; s >>= 1) { if (t < s) red[t] += red[t+s]; __syncthreads(); }
    float mu = red[0] * (1.f/384.f);
    __syncthreads();
    float d0 = v0-mu, d1 = v1-mu, d2 = v2-mu;
    red[t] = d0*d0 + d1*d1 + d2*d2;
    __syncthreads();
    #pragma unroll
    for (int s = 64; s > 0; s >>= 1) { if (t < s) red[t] += red[t+s]; __syncthreads(); }
    float inv = rsqrtf(red[0] * (1.f/384.f) + 1e-5f);
    out[i*DD + t]       = d0*inv*g[t]       + b[t];
    out[i*DD + t + 128] = d1*inv*g[t+128]   + b[t+128];
    out[i*DD + t + 256] = d2*inv*g[t+256]   + b[t+256];
}

// ---------------------------------------------------------------------------
extern "C" void kernel_launch(void* const* d_in, const int* in_sizes, int n_in,
                              void* d_out, int out_size) {
    const float* node  = (const float*)d_in[0];
    const float* edge  = (const float*)d_in[1];
    const float* rot   = (const float*)d_in[2];
    const float* trans = (const float*)d_in[3];
    const float* Wq_s = (const float*)d_in[5];
    const float* Wk_s = (const float*)d_in[6];
    const float* Wv_s = (const float*)d_in[7];
    const float* Wq_p = (const float*)d_in[8];
    const float* Wk_p = (const float*)d_in[9];
    const float* Wv_p = (const float*)d_in[10];
    const float* pw   = (const float*)d_in[11];
    const float* Wb   = (const float*)d_in[12];
    const float* bb   = (const float*)d_in[13];
    const float* Wo   = (const float*)d_in[14];
    const float* bo   = (const float*)d_in[15];
    const float* g1   = (const float*)d_in[16];
    const float* beta1= (const float*)d_in[17];
    const float* W1   = (const float*)d_in[18];
    const float* b1   = (const float*)d_in[19];
    const float* W2   = (const float*)d_in[20];
    const float* b2   = (const float*)d_in[21];
    const float* W3   = (const float*)d_in[22];
    const float* b3   = (const float*)d_in[23];
    const float* g2   = (const float*)d_in[24];
    const float* beta2= (const float*)d_in[25];
    float* out = (float*)d_out;

    float *p_cat, *p_t0, *p_t1, *p_t2, *p_t3, *p_x1;
    float *p_u0, *p_u1, *p_u2, *p_u3, *p_v0, *p_v1, *p_v2, *p_v3;
    float *p_proj;
    cudaGetSymbolAddress((void**)&p_cat, g_cat);
    cudaGetSymbolAddress((void**)&p_t0, g_t0);
    cudaGetSymbolAddress((void**)&p_t1, g_t1);
    cudaGetSymbolAddress((void**)&p_t2, g_t2);
    cudaGetSymbolAddress((void**)&p_t3, g_t3);
    cudaGetSymbolAddress((void**)&p_u0, g_u0);
    cudaGetSymbolAddress((void**)&p_u1, g_u1);
    cudaGetSymbolAddress((void**)&p_u2, g_u2);
    cudaGetSymbolAddress((void**)&p_u3, g_u3);
    cudaGetSymbolAddress((void**)&p_v0, g_v0);
    cudaGetSymbolAddress((void**)&p_v1, g_v1);
    cudaGetSymbolAddress((void**)&p_v2, g_v2);
    cudaGetSymbolAddress((void**)&p_v3, g_v3);
    cudaGetSymbolAddress((void**)&p_x1, g_x1);
    cudaGetSymbolAddress((void**)&p_proj, g_proj);

    k_gemmProj<<<dim3(16, 11), 128>>>(node, Wq_s, Wk_s, Wv_s, Wq_p, Wk_p, Wv_p, p_proj);
    k_post<<<NN, 128>>>(rot, trans);
    k_fused<<<dim3(NN, 8), 256>>>(edge, Wb, bb, pw);
    k_rs<<<dim3(16, 8, 4), 256>>>();
    k_cat<<<NN, 256>>>(rot, trans);

    // Wo: split-K 4 x 320 -> LN
    k_gemm64<CATD, DD><<<dim3(16, 6, 4), 128>>>(p_cat, Wo, bo, p_t0, p_t1, p_t2, p_t3, 320);
    k_ln4<<<NN, 128>>>(p_t0, p_t1, p_t2, p_t3, g1, beta1, p_x1);
    // W1: split-K 4 x 96 -> partials u
    k_gemm64<DD, HID><<<dim3(16, 12, 4), 128>>>(p_x1, W1, b1, p_u0, p_u1, p_u2, p_u3, 96);
    // W2: X = relu(sum u); split-K 4 x 192 -> partials v
    k_gemm64sum<HID, HID><<<dim3(16, 12, 4), 128>>>(p_u0, p_u1, p_u2, p_u3, W2, b2,
                                                    p_v0, p_v1, p_v2, p_v3, 192);
    // W3: X = relu(sum v); split-K 4 x 192 -> LN
    k_gemm64sum<HID, DD><<<dim3(16, 6, 4), 128>>>(p_v0, p_v1, p_v2, p_v3, W3, b3,
                                                  p_t0, p_t1, p_t2, p_t3, 192);
    k_ln4<<<NN, 128>>>(p_t0, p_t1, p_t2, p_t3, g2, beta2, out);
}